// round 10
// baseline (speedup 1.0000x reference)
#include <cuda_runtime.h>
#include <cuda_bf16.h>
#include <cstdint>

// VectorQuantizer: 1-product bf16 mma.sync screening + top-3/lane exact fp32
// rescore. x[128,2048,64] f32, W[512,64] f32.
// out = concat(quantized[16777216], loss[1], indices[262144]) f32.

#define KCODES 512
#define DIM 64
#define TILE_M 128
#define N_ROWS (128 * 2048)
#define N_TILES (N_ROWS / TILE_M)   // 2048
#define THREADS 256

#define WPITCH 144                  // bf16 row pitch (128B data + 16B pad) -> conflict-free ldmatrix

// ---- shared memory layout (bytes) ----
#define SM_B_HI   0                                  // 512 x WPITCH = 73728
#define SM_A_HI   (SM_B_HI + KCODES * WPITCH)        // 73728  (128 x WPITCH)
#define SM_XS     (SM_A_HI + TILE_M * WPITCH)        // 92160  : float[128][65]
#define SM_WSQ    (SM_XS + TILE_M * 65 * 4)          // 125440 : float[512]
#define SM_XSQ    (SM_WSQ + KCODES * 4)              // 127488
#define SM_MEAN   (SM_XSQ + TILE_M * 4)              // 128000
#define SM_DENOM  (SM_MEAN + TILE_M * 4)             // 128512
#define SM_IDX    (SM_DENOM + TILE_M * 4)            // 129024 : int[128]
#define SM_WACC   (SM_IDX + TILE_M * 4)              // 129536 : float[8]
#define SM_TOTAL  (SM_WACC + 128)                    // 129664 B (~127 KB)

__device__ float g_blockSums[N_TILES];

__device__ __forceinline__ uint32_t smem_u32(const void* p) {
    uint32_t a;
    asm("{ .reg .u64 t; cvta.to.shared.u64 t, %1; cvt.u32.u64 %0, t; }"
        : "=r"(a) : "l"(p));
    return a;
}

#define LDSM_X4(r0, r1, r2, r3, addr) \
    asm volatile("ldmatrix.sync.aligned.m8n8.x4.shared.b16 {%0,%1,%2,%3}, [%4];" \
        : "=r"(r0), "=r"(r1), "=r"(r2), "=r"(r3) : "r"(addr))

#define MMA_BF16(c, a, b) \
    asm volatile("mma.sync.aligned.m16n8k16.row.col.f32.bf16.bf16.f32 " \
        "{%0,%1,%2,%3}, {%4,%5,%6,%7}, {%8,%9}, {%0,%1,%2,%3};" \
        : "+f"((c)[0]), "+f"((c)[1]), "+f"((c)[2]), "+f"((c)[3]) \
        : "r"((a)[0]), "r"((a)[1]), "r"((a)[2]), "r"((a)[3]), \
          "r"((b)[0]), "r"((b)[1]))

// top-3 insertion, ascending column order, strict < (first-min semantics)
#define INS3(s, c, b1, i1, b2, i2, b3, i3) \
    do { \
        if ((s) < (b1)) { b3 = b2; i3 = i2; b2 = b1; i2 = i1; b1 = (s); i1 = (c); } \
        else if ((s) < (b2)) { b3 = b2; i3 = i2; b2 = (s); i2 = (c); } \
        else if ((s) < (b3)) { b3 = (s); i3 = (c); } \
    } while (0)

// Exact fp32 score, identical arithmetic order to the validated FFMA kernel.
__device__ __forceinline__ float exact_score(const float* __restrict__ xr,
                                             float xsq,
                                             const float* __restrict__ W,
                                             const float* __restrict__ WSQ,
                                             int k)
{
    const float4* wr = (const float4*)(W + (size_t)k * DIM);
    float a = 0.f;
    #pragma unroll
    for (int q = 0; q < DIM / 4; q++) {
        float4 b = wr[q];
        a = fmaf(xr[4 * q + 0], b.x, a);
        a = fmaf(xr[4 * q + 1], b.y, a);
        a = fmaf(xr[4 * q + 2], b.z, a);
        a = fmaf(xr[4 * q + 3], b.w, a);
    }
    return __fsub_rn(__fadd_rn(xsq, WSQ[k]), __fmul_rn(2.f, a));
}

__global__ void __launch_bounds__(THREADS, 1) vq_main(
    const float* __restrict__ x, const float* __restrict__ W,
    float* __restrict__ qout, float* __restrict__ idx_out)
{
    extern __shared__ char smc[];
    const uint32_t smb = smem_u32(smc);
    const int tid = threadIdx.x, wid = tid >> 5, lid = tid & 31;
    float* XS  = (float*)(smc + SM_XS);
    float* WSQ = (float*)(smc + SM_WSQ);
    float* XSQ = (float*)(smc + SM_XSQ);
    int*   IDX = (int*)(smc + SM_IDX);

    // ---- prologue: W fp32 -> bf16 smem tile (padded rows), x tile, wsq ----
    {
        const float4* Wg = (const float4*)W;
        #pragma unroll
        for (int i = tid; i < KCODES * DIM / 4; i += THREADS) {  // 8192
            float4 w4 = Wg[i];
            int row = i >> 4, col = (i & 15) * 4;
            __nv_bfloat162 p0 = __halves2bfloat162(__float2bfloat16(w4.x),
                                                   __float2bfloat16(w4.y));
            __nv_bfloat162 p1 = __halves2bfloat162(__float2bfloat16(w4.z),
                                                   __float2bfloat16(w4.w));
            uint2 v;
            v.x = *(uint32_t*)&p0;
            v.y = *(uint32_t*)&p1;
            *(uint2*)(smc + SM_B_HI + row * WPITCH + col * 2) = v;
        }
        const float4* xg = (const float4*)(x + (size_t)blockIdx.x * (TILE_M * DIM));
        #pragma unroll
        for (int i = tid; i < TILE_M * DIM / 4; i += THREADS) {
            float4 v4 = xg[i];
            int el = i * 4, r = el >> 6, dd = el & 63;
            float* p = XS + r * 65 + dd;
            p[0] = v4.x; p[1] = v4.y; p[2] = v4.z; p[3] = v4.w;
        }
        // wsq: exact sequential order per row (2 rows per thread)
        #pragma unroll
        for (int k = tid; k < KCODES; k += THREADS) {
            const float* w = W + (size_t)k * DIM;
            float s = 0.f;
            #pragma unroll
            for (int d = 0; d < DIM; d++) s = __fadd_rn(s, __fmul_rn(w[d], w[d]));
            WSQ[k] = s;
        }
    }
    __syncthreads();

    // ---- per-row normalization (exact sequential order, 1 thread/row) ----
    if (tid < TILE_M) {
        float v[DIM];
        float* xr = XS + tid * 65;
        #pragma unroll
        for (int d = 0; d < DIM; d++) v[d] = xr[d];
        float sum = 0.f;
        #pragma unroll
        for (int d = 0; d < DIM; d++) sum = __fadd_rn(sum, v[d]);
        float mean = __fmul_rn(sum, 0.015625f);
        float ss = 0.f;
        #pragma unroll
        for (int d = 0; d < DIM; d++) {
            float t = __fadd_rn(v[d], -mean);
            ss = __fadd_rn(ss, __fmul_rn(t, t));
        }
        float stdv  = __fsqrt_rn(__fdiv_rn(ss, 63.f));
        float denom = __fadd_rn(stdv, 1e-7f);
        float xsq = 0.f;
        #pragma unroll
        for (int d = 0; d < DIM; d++) {
            v[d] = __fdiv_rn(__fadd_rn(v[d], -mean), denom);
            xsq = __fadd_rn(xsq, __fmul_rn(v[d], v[d]));
            xr[d] = v[d];                       // exact xn kept for rescore/loss
        }
        // bf16 hi only, padded row for ldmatrix
        uint32_t base = (uint32_t)tid * WPITCH;
        #pragma unroll
        for (int q = 0; q < 8; q++) {
            uint32_t pkh[4];
            #pragma unroll
            for (int m = 0; m < 4; m++) {
                __nv_bfloat162 h2 = __halves2bfloat162(
                    __float2bfloat16(v[q * 8 + 2 * m]),
                    __float2bfloat16(v[q * 8 + 2 * m + 1]));
                pkh[m] = *(uint32_t*)&h2;
            }
            *(uint4*)(smc + SM_A_HI + base + q * 16) =
                make_uint4(pkh[0], pkh[1], pkh[2], pkh[3]);
        }
        XSQ[tid] = xsq;
        ((float*)(smc + SM_MEAN))[tid]  = mean;
        ((float*)(smc + SM_DENOM))[tid] = denom;
    }
    __syncthreads();

    // ---- warp MMA screening: C = Xhi * Whi^T (single product) ----
    {
        const int g = lid >> 2, t = lid & 3;
        const int row0 = wid * 16 + g, row1 = row0 + 8;

        const uint32_t aRow  = (uint32_t)(wid * 16 + ((lid & 8) ? 8 : 0) + (lid & 7));
        const uint32_t aKoff = (lid & 16) ? 16u : 0u;
        const uint32_t aHiA = smb + SM_A_HI + aRow * WPITCH + aKoff;

        uint32_t Ah[4][4];
        #pragma unroll
        for (int kc = 0; kc < 4; kc++)
            LDSM_X4(Ah[kc][0], Ah[kc][1], Ah[kc][2], Ah[kc][3], aHiA + kc * 32);

        const uint32_t bRsel = ((lid & 16) ? 8u : 0u) + (uint32_t)(lid & 7);
        const uint32_t bKoff = (lid & 8) ? 16u : 0u;

        // per-lane top-3 screening state, per row
        float b1r0 = 3.4e38f, b2r0 = 3.4e38f, b3r0 = 3.4e38f;
        float b1r1 = 3.4e38f, b2r1 = 3.4e38f, b3r1 = 3.4e38f;
        int i1r0 = 0, i2r0 = 0, i3r0 = 0;
        int i1r1 = 0, i2r1 = 0, i3r1 = 0;

        #pragma unroll 1
        for (int nc = 0; nc < 8; nc++) {
            float acc[8][4];
            #pragma unroll
            for (int i = 0; i < 8; i++) {
                acc[i][0] = 0.f; acc[i][1] = 0.f; acc[i][2] = 0.f; acc[i][3] = 0.f;
            }
            #pragma unroll
            for (int kc = 0; kc < 4; kc++) {
                uint32_t bh[8][2];
                #pragma unroll
                for (int p = 0; p < 4; p++) {
                    uint32_t nrow = (uint32_t)(nc * 64 + p * 16) + bRsel;
                    uint32_t boff = nrow * WPITCH + (uint32_t)kc * 32 + bKoff;
                    LDSM_X4(bh[2 * p][0], bh[2 * p][1],
                            bh[2 * p + 1][0], bh[2 * p + 1][1],
                            smb + SM_B_HI + boff);
                }
                #pragma unroll
                for (int nt = 0; nt < 8; nt++)
                    MMA_BF16(acc[nt], Ah[kc], bh[nt]);
            }
            // screening score: wsq - 2*dot (xsq row-constant, ordering-invariant)
            #pragma unroll
            for (int nt = 0; nt < 8; nt++) {
                int cb = nc * 64 + nt * 8 + 2 * t;
                float w0 = WSQ[cb], w1 = WSQ[cb + 1];
                float s;
                s = __fmaf_rn(-2.f, acc[nt][0], w0);
                INS3(s, cb,     b1r0, i1r0, b2r0, i2r0, b3r0, i3r0);
                s = __fmaf_rn(-2.f, acc[nt][1], w1);
                INS3(s, cb + 1, b1r0, i1r0, b2r0, i2r0, b3r0, i3r0);
                s = __fmaf_rn(-2.f, acc[nt][2], w0);
                INS3(s, cb,     b1r1, i1r1, b2r1, i2r1, b3r1, i3r1);
                s = __fmaf_rn(-2.f, acc[nt][3], w1);
                INS3(s, cb + 1, b1r1, i1r1, b2r1, i2r1, b3r1, i3r1);
            }
        }

        // ---- exact fp32 rescore of per-lane top-3 (12 candidates per row) ----
        const float xsq0 = XSQ[row0], xsq1 = XSQ[row1];
        const float* xr0 = XS + row0 * 65;
        const float* xr1 = XS + row1 * 65;

        float e1 = exact_score(xr0, xsq0, W, WSQ, i1r0);
        float e2 = exact_score(xr0, xsq0, W, WSQ, i2r0);
        float e3 = exact_score(xr0, xsq0, W, WSQ, i3r0);
        float best0 = e1; int bi0 = i1r0;
        if (e2 < best0 || (e2 == best0 && i2r0 < bi0)) { best0 = e2; bi0 = i2r0; }
        if (e3 < best0 || (e3 == best0 && i3r0 < bi0)) { best0 = e3; bi0 = i3r0; }

        e1 = exact_score(xr1, xsq1, W, WSQ, i1r1);
        e2 = exact_score(xr1, xsq1, W, WSQ, i2r1);
        e3 = exact_score(xr1, xsq1, W, WSQ, i3r1);
        float best1 = e1; int bi1 = i1r1;
        if (e2 < best1 || (e2 == best1 && i2r1 < bi1)) { best1 = e2; bi1 = i2r1; }
        if (e3 < best1 || (e3 == best1 && i3r1 < bi1)) { best1 = e3; bi1 = i3r1; }

        // reduce across the 4 lanes sharing a row (tie -> lowest index)
        #pragma unroll
        for (int off = 1; off <= 2; off <<= 1) {
            float sb = __shfl_xor_sync(0xffffffffu, best0, off);
            int   ib = __shfl_xor_sync(0xffffffffu, bi0, off);
            if (sb < best0 || (sb == best0 && ib < bi0)) { best0 = sb; bi0 = ib; }
            sb = __shfl_xor_sync(0xffffffffu, best1, off);
            ib = __shfl_xor_sync(0xffffffffu, bi1, off);
            if (sb < best1 || (sb == best1 && ib < bi1)) { best1 = sb; bi1 = ib; }
        }
        if (t == 0) { IDX[row0] = bi0; IDX[row1] = bi1; }
    }
    __syncthreads();

    // ---- exact gather/loss/denorm (tid < 128) ----
    if (tid < TILE_M) {
        int bi = IDX[tid];
        if (idx_out)
            idx_out[(size_t)blockIdx.x * TILE_M + tid] = (float)bi;
        float mean  = ((float*)(smc + SM_MEAN))[tid];
        float denom = ((float*)(smc + SM_DENOM))[tid];
        const float4* wr = (const float4*)(W + (size_t)bi * DIM);
        float* xr = XS + tid * 65;
        float lsum = 0.f;
        #pragma unroll
        for (int q = 0; q < DIM / 4; q++) {
            float4 b = wr[q];
            float d0 = b.x - xr[4 * q + 0];
            float d1 = b.y - xr[4 * q + 1];
            float d2 = b.z - xr[4 * q + 2];
            float d3 = b.w - xr[4 * q + 3];
            lsum = fmaf(d0, d0, lsum); lsum = fmaf(d1, d1, lsum);
            lsum = fmaf(d2, d2, lsum); lsum = fmaf(d3, d3, lsum);
            xr[4 * q + 0] = fmaf(b.x, denom, mean);
            xr[4 * q + 1] = fmaf(b.y, denom, mean);
            xr[4 * q + 2] = fmaf(b.z, denom, mean);
            xr[4 * q + 3] = fmaf(b.w, denom, mean);
        }
        #pragma unroll
        for (int off = 16; off; off >>= 1)
            lsum = __fadd_rn(lsum, __shfl_down_sync(0xffffffffu, lsum, off));
        if (lid == 0) ((float*)(smc + SM_WACC))[wid] = lsum;
    }
    __syncthreads();

    // ---- coalesced quantized store + block loss ----
    {
        float* og = qout + (size_t)blockIdx.x * (TILE_M * DIM);
        #pragma unroll
        for (int i = tid; i < TILE_M * DIM; i += THREADS)
            og[i] = XS[(i >> 6) * 65 + (i & 63)];
        if (tid == 0) {
            float* wa = (float*)(smc + SM_WACC);
            float s = wa[0];
            #pragma unroll
            for (int w2 = 1; w2 < 4; w2++) s = __fadd_rn(s, wa[w2]);
            g_blockSums[blockIdx.x] = s;
        }
    }
}

__global__ void vq_loss_kernel(float* __restrict__ loss_out) {
    __shared__ float sh[256];
    int t = threadIdx.x;
    float s = 0.f;
    #pragma unroll
    for (int i = 0; i < N_TILES / 256; i++)
        s = __fadd_rn(s, g_blockSums[t + i * 256]);
    sh[t] = s;
    __syncthreads();
    #pragma unroll
    for (int off = 128; off > 0; off >>= 1) {
        if (t < off) sh[t] = __fadd_rn(sh[t], sh[t + off]);
        __syncthreads();
    }
    if (t == 0)
        loss_out[0] = 1.25f * sh[0] * (1.0f / 16777216.0f);
}

extern "C" void kernel_launch(void* const* d_in, const int* in_sizes, int n_in,
                              void* d_out, int out_size)
{
    const float* x = (const float*)d_in[0];
    const float* W = (const float*)d_in[1];
    float* out = (float*)d_out;

    const long long q = (long long)N_ROWS * DIM;  // 16777216
    float* loss_out = nullptr;
    float* idx_out  = nullptr;
    long long osz = (long long)out_size;
    if (osz >= q + 1 + N_ROWS)      { loss_out = out + q; idx_out = out + q + 1; }
    else if (osz == q + N_ROWS)     { idx_out = out + q; }
    else if (osz == q + 1)          { loss_out = out + q; }

    cudaFuncSetAttribute(vq_main, cudaFuncAttributeMaxDynamicSharedMemorySize, SM_TOTAL);
    vq_main<<<N_TILES, THREADS, SM_TOTAL>>>(x, W, out, idx_out);
    if (loss_out)
        vq_loss_kernel<<<1, 256>>>(loss_out);
}

// round 14
// speedup vs baseline: 1.9249x; 1.9249x over previous
#include <cuda_runtime.h>
#include <cuda_bf16.h>
#include <cstdint>

// VectorQuantizer via warp-level mma.sync (2-product split-bf16: Ahi*Bhi + Alo*Bhi)
// + exact fp32 re-score of per-lane top-2 candidates (argmin fidelity).
// x[128,2048,64] f32, W[512,64] f32.
// out = concat(quantized[16777216], loss[1], indices[262144]) f32.

#define KCODES 512
#define DIM 64
#define TILE_M 128
#define N_ROWS (128 * 2048)
#define N_TILES (N_ROWS / TILE_M)   // 2048
#define THREADS 256

#define WPITCH 144                  // bf16 row pitch (128B data + 16B pad) -> conflict-free ldmatrix

// ---- shared memory layout (bytes) ----
#define SM_B_HI   0                                  // 512 x 144 = 73728
#define SM_A_HI   (SM_B_HI + KCODES * WPITCH)        // 73728
#define SM_A_LO   (SM_A_HI + TILE_M * WPITCH)        // 92160
#define SM_XS     (SM_A_LO + TILE_M * WPITCH)        // 110592 : float[128][65]
#define SM_WSQ    (SM_XS + TILE_M * 65 * 4)          // 143872 : float[512]
#define SM_XSQ    (SM_WSQ + KCODES * 4)              // 145920
#define SM_MEAN   (SM_XSQ + TILE_M * 4)              // 146432
#define SM_DENOM  (SM_MEAN + TILE_M * 4)             // 146944
#define SM_IDX    (SM_DENOM + TILE_M * 4)            // 147456 : int[128]
#define SM_WACC   (SM_IDX + TILE_M * 4)              // 147968 : float[8]
#define SM_TOTAL  (SM_WACC + 128)                    // 148096 B (~145 KB)

__device__ __nv_bfloat16 g_Whi[KCODES * DIM];
__device__ float g_wsq[KCODES];
__device__ float g_blockSums[N_TILES];

__device__ __forceinline__ uint32_t smem_u32(const void* p) {
    uint32_t a;
    asm("{ .reg .u64 t; cvta.to.shared.u64 t, %1; cvt.u32.u64 %0, t; }"
        : "=r"(a) : "l"(p));
    return a;
}

#define LDSM_X4(r0, r1, r2, r3, addr) \
    asm volatile("ldmatrix.sync.aligned.m8n8.x4.shared.b16 {%0,%1,%2,%3}, [%4];" \
        : "=r"(r0), "=r"(r1), "=r"(r2), "=r"(r3) : "r"(addr))

#define MMA_BF16(c, a, b) \
    asm volatile("mma.sync.aligned.m16n8k16.row.col.f32.bf16.bf16.f32 " \
        "{%0,%1,%2,%3}, {%4,%5,%6,%7}, {%8,%9}, {%0,%1,%2,%3};" \
        : "+f"((c)[0]), "+f"((c)[1]), "+f"((c)[2]), "+f"((c)[3]) \
        : "r"((a)[0]), "r"((a)[1]), "r"((a)[2]), "r"((a)[3]), \
          "r"((b)[0]), "r"((b)[1]))

// Exact fp32 score, identical arithmetic order to the validated FFMA kernel:
// dot accumulated by sequential fmaf in ascending d; score = (xsq+wsq) - 2*dot.
__device__ __forceinline__ float exact_score(const float* __restrict__ xr,
                                             float xsq,
                                             const float* __restrict__ W,
                                             const float* __restrict__ WSQ,
                                             int k)
{
    const float4* wr = (const float4*)(W + (size_t)k * DIM);
    float a = 0.f;
    #pragma unroll
    for (int q = 0; q < DIM / 4; q++) {
        float4 b = wr[q];
        a = fmaf(xr[4 * q + 0], b.x, a);
        a = fmaf(xr[4 * q + 1], b.y, a);
        a = fmaf(xr[4 * q + 2], b.z, a);
        a = fmaf(xr[4 * q + 3], b.w, a);
    }
    return __fsub_rn(__fadd_rn(xsq, WSQ[k]), __fmul_rn(2.f, a));
}

// ---------------- prep: W -> bf16 hi + wsq (16 blocks x 32 thr, 1 code/thread) ----------------
__global__ void vq_prep(const float* __restrict__ W) {
    int k = blockIdx.x * 32 + threadIdx.x;   // k in [0, 512)
    const float4* wr = (const float4*)(W + (size_t)k * DIM);
    float4 v[16];
    #pragma unroll
    for (int q = 0; q < 16; q++) v[q] = wr[q];   // pipelined independent loads
    float w[DIM];
    #pragma unroll
    for (int q = 0; q < 16; q++) {
        w[4 * q + 0] = v[q].x; w[4 * q + 1] = v[q].y;
        w[4 * q + 2] = v[q].z; w[4 * q + 3] = v[q].w;
    }
    float s = 0.f;
    #pragma unroll
    for (int d = 0; d < DIM; d++) s = __fadd_rn(s, __fmul_rn(w[d], w[d]));
    g_wsq[k] = s;
    uint2* dst = (uint2*)(g_Whi + (size_t)k * DIM);
    #pragma unroll
    for (int q = 0; q < 16; q++) {
        __nv_bfloat162 p0 = __halves2bfloat162(__float2bfloat16(w[4 * q + 0]),
                                               __float2bfloat16(w[4 * q + 1]));
        __nv_bfloat162 p1 = __halves2bfloat162(__float2bfloat16(w[4 * q + 2]),
                                               __float2bfloat16(w[4 * q + 3]));
        uint2 o;
        o.x = *(uint32_t*)&p0;
        o.y = *(uint32_t*)&p1;
        dst[q] = o;
    }
}

// ---------------- main ----------------
__global__ void __launch_bounds__(THREADS, 1) vq_main(
    const float* __restrict__ x, const float* __restrict__ W,
    float* __restrict__ qout, float* __restrict__ idx_out)
{
    extern __shared__ char smc[];
    const uint32_t smb = smem_u32(smc);
    const int tid = threadIdx.x, wid = tid >> 5, lid = tid & 31;
    float* XS   = (float*)(smc + SM_XS);
    float* WSQ  = (float*)(smc + SM_WSQ);
    float* XSQ  = (float*)(smc + SM_XSQ);
    int*   IDX  = (int*)(smc + SM_IDX);

    // ---- cooperative loads: W bf16 hi (padded rows) + wsq + x tile ----
    {
        const uint4* gh = (const uint4*)g_Whi;
        #pragma unroll
        for (int i = tid; i < KCODES * 8; i += THREADS) {   // 8 x uint4 per row
            int row = i >> 3, c = i & 7;
            uint32_t off = (uint32_t)(row * WPITCH + c * 16);
            *(uint4*)(smc + SM_B_HI + off) = gh[i];
        }
        for (int i = tid; i < KCODES; i += THREADS) WSQ[i] = g_wsq[i];
        const float4* xg = (const float4*)(x + (size_t)blockIdx.x * (TILE_M * DIM));
        #pragma unroll
        for (int i = tid; i < TILE_M * DIM / 4; i += THREADS) {
            float4 v4 = xg[i];
            int el = i * 4, r = el >> 6, dd = el & 63;
            float* p = XS + r * 65 + dd;
            p[0] = v4.x; p[1] = v4.y; p[2] = v4.z; p[3] = v4.w;
        }
    }
    __syncthreads();

    // ---- per-row normalization (exact sequential order, 1 thread/row) ----
    if (tid < TILE_M) {
        float v[DIM];
        float* xr = XS + tid * 65;
        #pragma unroll
        for (int d = 0; d < DIM; d++) v[d] = xr[d];
        float sum = 0.f;
        #pragma unroll
        for (int d = 0; d < DIM; d++) sum = __fadd_rn(sum, v[d]);
        float mean = __fmul_rn(sum, 0.015625f);
        float ss = 0.f;
        #pragma unroll
        for (int d = 0; d < DIM; d++) {
            float t = __fadd_rn(v[d], -mean);
            ss = __fadd_rn(ss, __fmul_rn(t, t));
        }
        float stdv  = __fsqrt_rn(__fdiv_rn(ss, 63.f));
        float denom = __fadd_rn(stdv, 1e-7f);
        float xsq = 0.f;
        #pragma unroll
        for (int d = 0; d < DIM; d++) {
            v[d] = __fdiv_rn(__fadd_rn(v[d], -mean), denom);
            xsq = __fadd_rn(xsq, __fmul_rn(v[d], v[d]));
            xr[d] = v[d];                       // keep exact xn for loss/rescore
        }
        // split to bf16 hi/lo, store padded rows for ldmatrix
        uint32_t base = (uint32_t)tid * WPITCH;
        #pragma unroll
        for (int q = 0; q < 8; q++) {
            uint32_t pkh[4], pkl[4];
            #pragma unroll
            for (int m = 0; m < 4; m++) {
                float a = v[q * 8 + 2 * m], b = v[q * 8 + 2 * m + 1];
                __nv_bfloat16 ha = __float2bfloat16(a), hb = __float2bfloat16(b);
                float la = __fadd_rn(a, -__bfloat162float(ha));
                float lb = __fadd_rn(b, -__bfloat162float(hb));
                __nv_bfloat162 h2 = __halves2bfloat162(ha, hb);
                __nv_bfloat162 l2 = __halves2bfloat162(__float2bfloat16(la),
                                                       __float2bfloat16(lb));
                pkh[m] = *(uint32_t*)&h2;
                pkl[m] = *(uint32_t*)&l2;
            }
            uint32_t off = base + q * 16;
            *(uint4*)(smc + SM_A_HI + off) = make_uint4(pkh[0], pkh[1], pkh[2], pkh[3]);
            *(uint4*)(smc + SM_A_LO + off) = make_uint4(pkl[0], pkl[1], pkl[2], pkl[3]);
        }
        XSQ[tid] = xsq;
        ((float*)(smc + SM_MEAN))[tid]  = mean;
        ((float*)(smc + SM_DENOM))[tid] = denom;
    }
    __syncthreads();

    // ---- warp MMA: C[128,512] = Xhi*Whi^T + Xlo*Whi^T ----
    {
        const int g = lid >> 2, t = lid & 3;
        const int row0 = wid * 16 + g, row1 = row0 + 8;
        const float xsq0 = XSQ[row0], xsq1 = XSQ[row1];

        // A fragment addresses (lane-mapped for ldmatrix.x4)
        const uint32_t aRow  = (uint32_t)(wid * 16 + ((lid & 8) ? 8 : 0) + (lid & 7));
        const uint32_t aKoff = (lid & 16) ? 16u : 0u;
        const uint32_t aHiA = smb + SM_A_HI + aRow * WPITCH + aKoff;
        const uint32_t aLoA = smb + SM_A_LO + aRow * WPITCH + aKoff;

        uint32_t Ah[4][4], Al[4][4];
        #pragma unroll
        for (int kc = 0; kc < 4; kc++) {
            LDSM_X4(Ah[kc][0], Ah[kc][1], Ah[kc][2], Ah[kc][3], aHiA + kc * 32);
            LDSM_X4(Al[kc][0], Al[kc][1], Al[kc][2], Al[kc][3], aLoA + kc * 32);
        }

        // B fragment lane mapping
        const uint32_t bRsel = ((lid & 16) ? 8u : 0u) + (uint32_t)(lid & 7);
        const uint32_t bKoff = (lid & 8) ? 16u : 0u;

        // per-lane top-2 (mma scores) for each of the 2 rows
        float b1r0 = 3.402823466e38f, b2r0 = 3.402823466e38f;
        float b1r1 = 3.402823466e38f, b2r1 = 3.402823466e38f;
        int i1r0 = 0, i2r0 = 0, i1r1 = 0, i2r1 = 0;

        #pragma unroll 1
        for (int nc = 0; nc < 8; nc++) {
            float acc[8][4];
            #pragma unroll
            for (int i = 0; i < 8; i++) {
                acc[i][0] = 0.f; acc[i][1] = 0.f; acc[i][2] = 0.f; acc[i][3] = 0.f;
            }
            #pragma unroll
            for (int kc = 0; kc < 4; kc++) {
                uint32_t bh[8][2];
                #pragma unroll
                for (int p = 0; p < 4; p++) {
                    uint32_t nrow = (uint32_t)(nc * 64 + p * 16) + bRsel;
                    uint32_t boff = nrow * WPITCH + (uint32_t)kc * 32 + bKoff;
                    LDSM_X4(bh[2 * p][0], bh[2 * p][1], bh[2 * p + 1][0], bh[2 * p + 1][1],
                            smb + SM_B_HI + boff);
                }
                #pragma unroll
                for (int nt = 0; nt < 8; nt++) {
                    MMA_BF16(acc[nt], Ah[kc], bh[nt]);
                    MMA_BF16(acc[nt], Al[kc], bh[nt]);
                }
            }
            // scores + top-2 tracking (ascending column order, strict <)
            #pragma unroll
            for (int nt = 0; nt < 8; nt++) {
                int cb = nc * 64 + nt * 8 + 2 * t;
                float w0 = WSQ[cb], w1 = WSQ[cb + 1];
                float s;
                s = __fsub_rn(__fadd_rn(xsq0, w0), __fmul_rn(2.f, acc[nt][0]));
                if (s < b1r0) { b2r0 = b1r0; i2r0 = i1r0; b1r0 = s; i1r0 = cb; }
                else if (s < b2r0) { b2r0 = s; i2r0 = cb; }
                s = __fsub_rn(__fadd_rn(xsq0, w1), __fmul_rn(2.f, acc[nt][1]));
                if (s < b1r0) { b2r0 = b1r0; i2r0 = i1r0; b1r0 = s; i1r0 = cb + 1; }
                else if (s < b2r0) { b2r0 = s; i2r0 = cb + 1; }
                s = __fsub_rn(__fadd_rn(xsq1, w0), __fmul_rn(2.f, acc[nt][2]));
                if (s < b1r1) { b2r1 = b1r1; i2r1 = i1r1; b1r1 = s; i1r1 = cb; }
                else if (s < b2r1) { b2r1 = s; i2r1 = cb; }
                s = __fsub_rn(__fadd_rn(xsq1, w1), __fmul_rn(2.f, acc[nt][3]));
                if (s < b1r1) { b2r1 = b1r1; i2r1 = i1r1; b1r1 = s; i1r1 = cb + 1; }
                else if (s < b2r1) { b2r1 = s; i2r1 = cb + 1; }
            }
        }

        // ---- exact fp32 rescore of the per-lane top-2 candidates ----
        const float* xr0 = XS + row0 * 65;
        const float* xr1 = XS + row1 * 65;
        float e1 = exact_score(xr0, xsq0, W, WSQ, i1r0);
        float e2 = exact_score(xr0, xsq0, W, WSQ, i2r0);
        float best0; int bi0;
        if (e2 < e1 || (e2 == e1 && i2r0 < i1r0)) { best0 = e2; bi0 = i2r0; }
        else                                      { best0 = e1; bi0 = i1r0; }
        e1 = exact_score(xr1, xsq1, W, WSQ, i1r1);
        e2 = exact_score(xr1, xsq1, W, WSQ, i2r1);
        float best1; int bi1;
        if (e2 < e1 || (e2 == e1 && i2r1 < i1r1)) { best1 = e2; bi1 = i2r1; }
        else                                      { best1 = e1; bi1 = i1r1; }

        // reduce across the 4 lanes sharing a row (tie -> lowest index)
        #pragma unroll
        for (int off = 1; off <= 2; off <<= 1) {
            float sb = __shfl_xor_sync(0xffffffffu, best0, off);
            int   ib = __shfl_xor_sync(0xffffffffu, bi0, off);
            if (sb < best0 || (sb == best0 && ib < bi0)) { best0 = sb; bi0 = ib; }
            sb = __shfl_xor_sync(0xffffffffu, best1, off);
            ib = __shfl_xor_sync(0xffffffffu, bi1, off);
            if (sb < best1 || (sb == best1 && ib < bi1)) { best1 = sb; bi1 = ib; }
        }
        if (t == 0) { IDX[row0] = bi0; IDX[row1] = bi1; }
    }
    __syncthreads();

    // ---- exact gather/loss/denorm (tid < 128) ----
    if (tid < TILE_M) {
        int bi = IDX[tid];
        if (idx_out)
            idx_out[(size_t)blockIdx.x * TILE_M + tid] = (float)bi;
        float mean  = ((float*)(smc + SM_MEAN))[tid];
        float denom = ((float*)(smc + SM_DENOM))[tid];
        const float4* wr = (const float4*)(W + (size_t)bi * DIM);
        float* xr = XS + tid * 65;
        float lsum = 0.f;
        #pragma unroll
        for (int q = 0; q < DIM / 4; q++) {
            float4 b = wr[q];
            float d0 = b.x - xr[4 * q + 0];
            float d1 = b.y - xr[4 * q + 1];
            float d2 = b.z - xr[4 * q + 2];
            float d3 = b.w - xr[4 * q + 3];
            lsum = fmaf(d0, d0, lsum); lsum = fmaf(d1, d1, lsum);
            lsum = fmaf(d2, d2, lsum); lsum = fmaf(d3, d3, lsum);
            xr[4 * q + 0] = fmaf(b.x, denom, mean);
            xr[4 * q + 1] = fmaf(b.y, denom, mean);
            xr[4 * q + 2] = fmaf(b.z, denom, mean);
            xr[4 * q + 3] = fmaf(b.w, denom, mean);
        }
        #pragma unroll
        for (int off = 16; off; off >>= 1)
            lsum = __fadd_rn(lsum, __shfl_down_sync(0xffffffffu, lsum, off));
        if (lid == 0) ((float*)(smc + SM_WACC))[wid] = lsum;
    }
    __syncthreads();

    // ---- coalesced quantized store + block loss ----
    {
        float* og = qout + (size_t)blockIdx.x * (TILE_M * DIM);
        #pragma unroll
        for (int i = tid; i < TILE_M * DIM; i += THREADS)
            og[i] = XS[(i >> 6) * 65 + (i & 63)];
        if (tid == 0) {
            float* wa = (float*)(smc + SM_WACC);
            float s = wa[0];
            #pragma unroll
            for (int w2 = 1; w2 < 4; w2++) s = __fadd_rn(s, wa[w2]);
            g_blockSums[blockIdx.x] = s;
        }
    }
}

__global__ void vq_loss_kernel(float* __restrict__ loss_out) {
    __shared__ float sh[256];
    int t = threadIdx.x;
    float s = 0.f;
    #pragma unroll
    for (int i = 0; i < N_TILES / 256; i++)
        s = __fadd_rn(s, g_blockSums[t + i * 256]);
    sh[t] = s;
    __syncthreads();
    #pragma unroll
    for (int off = 128; off > 0; off >>= 1) {
        if (t < off) sh[t] = __fadd_rn(sh[t], sh[t + off]);
        __syncthreads();
    }
    if (t == 0)
        loss_out[0] = 1.25f * sh[0] * (1.0f / 16777216.0f);
}

extern "C" void kernel_launch(void* const* d_in, const int* in_sizes, int n_in,
                              void* d_out, int out_size)
{
    const float* x = (const float*)d_in[0];
    const float* W = (const float*)d_in[1];
    float* out = (float*)d_out;

    const long long q = (long long)N_ROWS * DIM;  // 16777216
    float* loss_out = nullptr;
    float* idx_out  = nullptr;
    long long osz = (long long)out_size;
    if (osz >= q + 1 + N_ROWS)      { loss_out = out + q; idx_out = out + q + 1; }
    else if (osz == q + N_ROWS)     { idx_out = out + q; }
    else if (osz == q + 1)          { loss_out = out + q; }

    cudaFuncSetAttribute(vq_main, cudaFuncAttributeMaxDynamicSharedMemorySize, SM_TOTAL);
    vq_prep<<<16, 32>>>(W);
    vq_main<<<N_TILES, THREADS, SM_TOTAL>>>(x, W, out, idx_out);
    if (loss_out)
        vq_loss_kernel<<<1, 256>>>(loss_out);
}

// round 15
// speedup vs baseline: 2.1039x; 1.0930x over previous
#include <cuda_runtime.h>
#include <cuda_bf16.h>
#include <cstdint>

// VectorQuantizer via warp-level mma.sync (1-product screening: Ahi*Bhi)
// + exact fp32 re-score of per-lane top-2 candidates (argmin fidelity).
// x[128,2048,64] f32, W[512,64] f32.
// out = concat(quantized[16777216], loss[1], indices[262144]) f32.

#define KCODES 512
#define DIM 64
#define TILE_M 128
#define N_ROWS (128 * 2048)
#define N_TILES (N_ROWS / TILE_M)   // 2048
#define THREADS 256

#define WPITCH 144                  // bf16 row pitch (128B data + 16B pad) -> conflict-free ldmatrix

// ---- shared memory layout (bytes) ----
#define SM_B_HI   0                                  // 512 x 144 = 73728
#define SM_A_HI   (SM_B_HI + KCODES * WPITCH)        // 73728
#define SM_XS     (SM_A_HI + TILE_M * WPITCH)        // 92160  : float[128][65]
#define SM_WSQ    (SM_XS + TILE_M * 65 * 4)          // 125440 : float[512]
#define SM_XSQ    (SM_WSQ + KCODES * 4)              // 127488
#define SM_MEAN   (SM_XSQ + TILE_M * 4)              // 128000
#define SM_DENOM  (SM_MEAN + TILE_M * 4)             // 128512
#define SM_IDX    (SM_DENOM + TILE_M * 4)            // 129024 : int[128]
#define SM_WACC   (SM_IDX + TILE_M * 4)              // 129536 : float[8]
#define SM_TOTAL  (SM_WACC + 128)                    // 129664 B (~127 KB)

__device__ __nv_bfloat16 g_Whi[KCODES * DIM];
__device__ float g_wsq[KCODES];
__device__ float g_blockSums[N_TILES];

__device__ __forceinline__ uint32_t smem_u32(const void* p) {
    uint32_t a;
    asm("{ .reg .u64 t; cvta.to.shared.u64 t, %1; cvt.u32.u64 %0, t; }"
        : "=r"(a) : "l"(p));
    return a;
}

#define LDSM_X4(r0, r1, r2, r3, addr) \
    asm volatile("ldmatrix.sync.aligned.m8n8.x4.shared.b16 {%0,%1,%2,%3}, [%4];" \
        : "=r"(r0), "=r"(r1), "=r"(r2), "=r"(r3) : "r"(addr))

#define MMA_BF16(c, a, b) \
    asm volatile("mma.sync.aligned.m16n8k16.row.col.f32.bf16.bf16.f32 " \
        "{%0,%1,%2,%3}, {%4,%5,%6,%7}, {%8,%9}, {%0,%1,%2,%3};" \
        : "+f"((c)[0]), "+f"((c)[1]), "+f"((c)[2]), "+f"((c)[3]) \
        : "r"((a)[0]), "r"((a)[1]), "r"((a)[2]), "r"((a)[3]), \
          "r"((b)[0]), "r"((b)[1]))

// Exact fp32 score, identical arithmetic order to the validated FFMA kernel:
// dot accumulated by sequential fmaf in ascending d; score = (xsq+wsq) - 2*dot.
__device__ __forceinline__ float exact_score(const float* __restrict__ xr,
                                             float xsq,
                                             const float* __restrict__ W,
                                             const float* __restrict__ WSQ,
                                             int k)
{
    const float4* wr = (const float4*)(W + (size_t)k * DIM);
    float a = 0.f;
    #pragma unroll
    for (int q = 0; q < DIM / 4; q++) {
        float4 b = wr[q];
        a = fmaf(xr[4 * q + 0], b.x, a);
        a = fmaf(xr[4 * q + 1], b.y, a);
        a = fmaf(xr[4 * q + 2], b.z, a);
        a = fmaf(xr[4 * q + 3], b.w, a);
    }
    return __fsub_rn(__fadd_rn(xsq, WSQ[k]), __fmul_rn(2.f, a));
}

// ---------------- prep: W -> bf16 hi + wsq (16 blocks x 32 thr, 1 code/thread) ----------------
__global__ void vq_prep(const float* __restrict__ W) {
    int k = blockIdx.x * 32 + threadIdx.x;   // k in [0, 512)
    const float4* wr = (const float4*)(W + (size_t)k * DIM);
    float4 v[16];
    #pragma unroll
    for (int q = 0; q < 16; q++) v[q] = wr[q];   // pipelined independent loads
    float w[DIM];
    #pragma unroll
    for (int q = 0; q < 16; q++) {
        w[4 * q + 0] = v[q].x; w[4 * q + 1] = v[q].y;
        w[4 * q + 2] = v[q].z; w[4 * q + 3] = v[q].w;
    }
    float s = 0.f;
    #pragma unroll
    for (int d = 0; d < DIM; d++) s = __fadd_rn(s, __fmul_rn(w[d], w[d]));
    g_wsq[k] = s;
    uint2* dst = (uint2*)(g_Whi + (size_t)k * DIM);
    #pragma unroll
    for (int q = 0; q < 16; q++) {
        __nv_bfloat162 p0 = __halves2bfloat162(__float2bfloat16(w[4 * q + 0]),
                                               __float2bfloat16(w[4 * q + 1]));
        __nv_bfloat162 p1 = __halves2bfloat162(__float2bfloat16(w[4 * q + 2]),
                                               __float2bfloat16(w[4 * q + 3]));
        uint2 o;
        o.x = *(uint32_t*)&p0;
        o.y = *(uint32_t*)&p1;
        dst[q] = o;
    }
}

// ---------------- main ----------------
__global__ void __launch_bounds__(THREADS, 1) vq_main(
    const float* __restrict__ x, const float* __restrict__ W,
    float* __restrict__ qout, float* __restrict__ idx_out)
{
    extern __shared__ char smc[];
    const uint32_t smb = smem_u32(smc);
    const int tid = threadIdx.x, wid = tid >> 5, lid = tid & 31;
    float* XS   = (float*)(smc + SM_XS);
    float* WSQ  = (float*)(smc + SM_WSQ);
    float* XSQ  = (float*)(smc + SM_XSQ);
    int*   IDX  = (int*)(smc + SM_IDX);

    // ---- cooperative loads: W bf16 hi (padded rows) + wsq + x tile ----
    {
        const uint4* gh = (const uint4*)g_Whi;
        #pragma unroll
        for (int i = tid; i < KCODES * 8; i += THREADS) {   // 8 x uint4 per row
            int row = i >> 3, c = i & 7;
            uint32_t off = (uint32_t)(row * WPITCH + c * 16);
            *(uint4*)(smc + SM_B_HI + off) = gh[i];
        }
        for (int i = tid; i < KCODES; i += THREADS) WSQ[i] = g_wsq[i];
        const float4* xg = (const float4*)(x + (size_t)blockIdx.x * (TILE_M * DIM));
        #pragma unroll
        for (int i = tid; i < TILE_M * DIM / 4; i += THREADS) {
            float4 v4 = xg[i];
            int el = i * 4, r = el >> 6, dd = el & 63;
            float* p = XS + r * 65 + dd;
            p[0] = v4.x; p[1] = v4.y; p[2] = v4.z; p[3] = v4.w;
        }
    }
    __syncthreads();

    // ---- per-row normalization (exact sequential order, 1 thread/row) ----
    if (tid < TILE_M) {
        float v[DIM];
        float* xr = XS + tid * 65;
        #pragma unroll
        for (int d = 0; d < DIM; d++) v[d] = xr[d];
        float sum = 0.f;
        #pragma unroll
        for (int d = 0; d < DIM; d++) sum = __fadd_rn(sum, v[d]);
        float mean = __fmul_rn(sum, 0.015625f);
        float ss = 0.f;
        #pragma unroll
        for (int d = 0; d < DIM; d++) {
            float t = __fadd_rn(v[d], -mean);
            ss = __fadd_rn(ss, __fmul_rn(t, t));
        }
        float stdv  = __fsqrt_rn(__fdiv_rn(ss, 63.f));
        float denom = __fadd_rn(stdv, 1e-7f);
        float xsq = 0.f;
        #pragma unroll
        for (int d = 0; d < DIM; d++) {
            v[d] = __fdiv_rn(__fadd_rn(v[d], -mean), denom);
            xsq = __fadd_rn(xsq, __fmul_rn(v[d], v[d]));
            xr[d] = v[d];                       // keep exact xn for loss/rescore
        }
        // bf16 hi only, padded row for ldmatrix
        uint32_t base = (uint32_t)tid * WPITCH;
        #pragma unroll
        for (int q = 0; q < 8; q++) {
            uint32_t pkh[4];
            #pragma unroll
            for (int m = 0; m < 4; m++) {
                __nv_bfloat162 h2 = __halves2bfloat162(
                    __float2bfloat16(v[q * 8 + 2 * m]),
                    __float2bfloat16(v[q * 8 + 2 * m + 1]));
                pkh[m] = *(uint32_t*)&h2;
            }
            *(uint4*)(smc + SM_A_HI + base + q * 16) =
                make_uint4(pkh[0], pkh[1], pkh[2], pkh[3]);
        }
        XSQ[tid] = xsq;
        ((float*)(smc + SM_MEAN))[tid]  = mean;
        ((float*)(smc + SM_DENOM))[tid] = denom;
    }
    __syncthreads();

    // ---- warp MMA screening: C[128,512] = Xhi * Whi^T ----
    {
        const int g = lid >> 2, t = lid & 3;
        const int row0 = wid * 16 + g, row1 = row0 + 8;
        const float xsq0 = XSQ[row0], xsq1 = XSQ[row1];

        // A fragment addresses (lane-mapped for ldmatrix.x4)
        const uint32_t aRow  = (uint32_t)(wid * 16 + ((lid & 8) ? 8 : 0) + (lid & 7));
        const uint32_t aKoff = (lid & 16) ? 16u : 0u;
        const uint32_t aHiA = smb + SM_A_HI + aRow * WPITCH + aKoff;

        uint32_t Ah[4][4];
        #pragma unroll
        for (int kc = 0; kc < 4; kc++)
            LDSM_X4(Ah[kc][0], Ah[kc][1], Ah[kc][2], Ah[kc][3], aHiA + kc * 32);

        // B fragment lane mapping
        const uint32_t bRsel = ((lid & 16) ? 8u : 0u) + (uint32_t)(lid & 7);
        const uint32_t bKoff = (lid & 8) ? 16u : 0u;

        // per-lane top-2 (mma scores) for each of the 2 rows
        float b1r0 = 3.402823466e38f, b2r0 = 3.402823466e38f;
        float b1r1 = 3.402823466e38f, b2r1 = 3.402823466e38f;
        int i1r0 = 0, i2r0 = 0, i1r1 = 0, i2r1 = 0;

        #pragma unroll 1
        for (int nc = 0; nc < 8; nc++) {
            float acc[8][4];
            #pragma unroll
            for (int i = 0; i < 8; i++) {
                acc[i][0] = 0.f; acc[i][1] = 0.f; acc[i][2] = 0.f; acc[i][3] = 0.f;
            }
            #pragma unroll
            for (int kc = 0; kc < 4; kc++) {
                uint32_t bh[8][2];
                #pragma unroll
                for (int p = 0; p < 4; p++) {
                    uint32_t nrow = (uint32_t)(nc * 64 + p * 16) + bRsel;
                    uint32_t boff = nrow * WPITCH + (uint32_t)kc * 32 + bKoff;
                    LDSM_X4(bh[2 * p][0], bh[2 * p][1], bh[2 * p + 1][0], bh[2 * p + 1][1],
                            smb + SM_B_HI + boff);
                }
                #pragma unroll
                for (int nt = 0; nt < 8; nt++)
                    MMA_BF16(acc[nt], Ah[kc], bh[nt]);
            }
            // scores + top-2 tracking (ascending column order, strict <)
            #pragma unroll
            for (int nt = 0; nt < 8; nt++) {
                int cb = nc * 64 + nt * 8 + 2 * t;
                float w0 = WSQ[cb], w1 = WSQ[cb + 1];
                float s;
                s = __fsub_rn(__fadd_rn(xsq0, w0), __fmul_rn(2.f, acc[nt][0]));
                if (s < b1r0) { b2r0 = b1r0; i2r0 = i1r0; b1r0 = s; i1r0 = cb; }
                else if (s < b2r0) { b2r0 = s; i2r0 = cb; }
                s = __fsub_rn(__fadd_rn(xsq0, w1), __fmul_rn(2.f, acc[nt][1]));
                if (s < b1r0) { b2r0 = b1r0; i2r0 = i1r0; b1r0 = s; i1r0 = cb + 1; }
                else if (s < b2r0) { b2r0 = s; i2r0 = cb + 1; }
                s = __fsub_rn(__fadd_rn(xsq1, w0), __fmul_rn(2.f, acc[nt][2]));
                if (s < b1r1) { b2r1 = b1r1; i2r1 = i1r1; b1r1 = s; i1r1 = cb; }
                else if (s < b2r1) { b2r1 = s; i2r1 = cb; }
                s = __fsub_rn(__fadd_rn(xsq1, w1), __fmul_rn(2.f, acc[nt][3]));
                if (s < b1r1) { b2r1 = b1r1; i2r1 = i1r1; b1r1 = s; i1r1 = cb + 1; }
                else if (s < b2r1) { b2r1 = s; i2r1 = cb + 1; }
            }
        }

        // ---- exact fp32 rescore of the per-lane top-2 candidates ----
        const float* xr0 = XS + row0 * 65;
        const float* xr1 = XS + row1 * 65;
        float e1 = exact_score(xr0, xsq0, W, WSQ, i1r0);
        float e2 = exact_score(xr0, xsq0, W, WSQ, i2r0);
        float best0; int bi0;
        if (e2 < e1 || (e2 == e1 && i2r0 < i1r0)) { best0 = e2; bi0 = i2r0; }
        else                                      { best0 = e1; bi0 = i1r0; }
        e1 = exact_score(xr1, xsq1, W, WSQ, i1r1);
        e2 = exact_score(xr1, xsq1, W, WSQ, i2r1);
        float best1; int bi1;
        if (e2 < e1 || (e2 == e1 && i2r1 < i1r1)) { best1 = e2; bi1 = i2r1; }
        else                                      { best1 = e1; bi1 = i1r1; }

        // reduce across the 4 lanes sharing a row (tie -> lowest index)
        #pragma unroll
        for (int off = 1; off <= 2; off <<= 1) {
            float sb = __shfl_xor_sync(0xffffffffu, best0, off);
            int   ib = __shfl_xor_sync(0xffffffffu, bi0, off);
            if (sb < best0 || (sb == best0 && ib < bi0)) { best0 = sb; bi0 = ib; }
            sb = __shfl_xor_sync(0xffffffffu, best1, off);
            ib = __shfl_xor_sync(0xffffffffu, bi1, off);
            if (sb < best1 || (sb == best1 && ib < bi1)) { best1 = sb; bi1 = ib; }
        }
        if (t == 0) { IDX[row0] = bi0; IDX[row1] = bi1; }
    }
    __syncthreads();

    // ---- exact gather/loss/denorm (tid < 128) ----
    if (tid < TILE_M) {
        int bi = IDX[tid];
        if (idx_out)
            idx_out[(size_t)blockIdx.x * TILE_M + tid] = (float)bi;
        float mean  = ((float*)(smc + SM_MEAN))[tid];
        float denom = ((float*)(smc + SM_DENOM))[tid];
        const float4* wr = (const float4*)(W + (size_t)bi * DIM);
        float* xr = XS + tid * 65;
        float lsum = 0.f;
        #pragma unroll
        for (int q = 0; q < DIM / 4; q++) {
            float4 b = wr[q];
            float d0 = b.x - xr[4 * q + 0];
            float d1 = b.y - xr[4 * q + 1];
            float d2 = b.z - xr[4 * q + 2];
            float d3 = b.w - xr[4 * q + 3];
            lsum = fmaf(d0, d0, lsum); lsum = fmaf(d1, d1, lsum);
            lsum = fmaf(d2, d2, lsum); lsum = fmaf(d3, d3, lsum);
            xr[4 * q + 0] = fmaf(b.x, denom, mean);
            xr[4 * q + 1] = fmaf(b.y, denom, mean);
            xr[4 * q + 2] = fmaf(b.z, denom, mean);
            xr[4 * q + 3] = fmaf(b.w, denom, mean);
        }
        #pragma unroll
        for (int off = 16; off; off >>= 1)
            lsum = __fadd_rn(lsum, __shfl_down_sync(0xffffffffu, lsum, off));
        if (lid == 0) ((float*)(smc + SM_WACC))[wid] = lsum;
    }
    __syncthreads();

    // ---- coalesced quantized store + block loss ----
    {
        float* og = qout + (size_t)blockIdx.x * (TILE_M * DIM);
        #pragma unroll
        for (int i = tid; i < TILE_M * DIM; i += THREADS)
            og[i] = XS[(i >> 6) * 65 + (i & 63)];
        if (tid == 0) {
            float* wa = (float*)(smc + SM_WACC);
            float s = wa[0];
            #pragma unroll
            for (int w2 = 1; w2 < 4; w2++) s = __fadd_rn(s, wa[w2]);
            g_blockSums[blockIdx.x] = s;
        }
    }
}

__global__ void vq_loss_kernel(float* __restrict__ loss_out) {
    __shared__ float sh[256];
    int t = threadIdx.x;
    float s = 0.f;
    #pragma unroll
    for (int i = 0; i < N_TILES / 256; i++)
        s = __fadd_rn(s, g_blockSums[t + i * 256]);
    sh[t] = s;
    __syncthreads();
    #pragma unroll
    for (int off = 128; off > 0; off >>= 1) {
        if (t < off) sh[t] = __fadd_rn(sh[t], sh[t + off]);
        __syncthreads();
    }
    if (t == 0)
        loss_out[0] = 1.25f * sh[0] * (1.0f / 16777216.0f);
}

extern "C" void kernel_launch(void* const* d_in, const int* in_sizes, int n_in,
                              void* d_out, int out_size)
{
    const float* x = (const float*)d_in[0];
    const float* W = (const float*)d_in[1];
    float* out = (float*)d_out;

    const long long q = (long long)N_ROWS * DIM;  // 16777216
    float* loss_out = nullptr;
    float* idx_out  = nullptr;
    long long osz = (long long)out_size;
    if (osz >= q + 1 + N_ROWS)      { loss_out = out + q; idx_out = out + q + 1; }
    else if (osz == q + N_ROWS)     { idx_out = out + q; }
    else if (osz == q + 1)          { loss_out = out + q; }

    cudaFuncSetAttribute(vq_main, cudaFuncAttributeMaxDynamicSharedMemorySize, SM_TOTAL);
    vq_prep<<<16, 32>>>(W);
    vq_main<<<N_TILES, THREADS, SM_TOTAL>>>(x, W, out, idx_out);
    if (loss_out)
        vq_loss_kernel<<<1, 256>>>(loss_out);
}

// round 17
// speedup vs baseline: 2.4245x; 1.1524x over previous
#include <cuda_runtime.h>
#include <cuda_bf16.h>
#include <cstdint>

// VectorQuantizer via warp-level mma.sync (1-product screening: Ahi*Bhi)
// + exact fp32 re-score of per-lane top-2 candidates (argmin fidelity).
// TILE_M=256 rows/CTA, 512 threads, warp-specialized prologue.
// x[128,2048,64] f32, W[512,64] f32.
// out = concat(quantized[16777216], loss[1], indices[262144]) f32.

#define KCODES 512
#define DIM 64
#define TILE_M 256
#define N_ROWS (128 * 2048)
#define N_TILES (N_ROWS / TILE_M)   // 1024
#define THREADS 512

#define WPITCH 144                  // bf16 row pitch (128B data + 16B pad) -> conflict-free ldmatrix

// ---- shared memory layout (bytes) ----
#define SM_B_HI   0                                  // 512 x 144 = 73728
#define SM_A_HI   (SM_B_HI + KCODES * WPITCH)        // 73728  (256 x 144)
#define SM_XS     (SM_A_HI + TILE_M * WPITCH)        // 110592 : float[256][65]
#define SM_WSQ    (SM_XS + TILE_M * 65 * 4)          // 177152 : float[512]
#define SM_XSQ    (SM_WSQ + KCODES * 4)              // 179200
#define SM_MEAN   (SM_XSQ + TILE_M * 4)              // 180224
#define SM_DENOM  (SM_MEAN + TILE_M * 4)             // 181248
#define SM_IDX    (SM_DENOM + TILE_M * 4)            // 182272 : int[256]
#define SM_WACC   (SM_IDX + TILE_M * 4)              // 183296 : float[8]
#define SM_TOTAL  (SM_WACC + 128)                    // 183424 B (~179 KB)

__device__ __nv_bfloat16 g_Whi[KCODES * DIM];
__device__ float g_wsq[KCODES];
__device__ float g_blockSums[N_TILES];

__device__ __forceinline__ uint32_t smem_u32(const void* p) {
    uint32_t a;
    asm("{ .reg .u64 t; cvta.to.shared.u64 t, %1; cvt.u32.u64 %0, t; }"
        : "=r"(a) : "l"(p));
    return a;
}

#define LDSM_X4(r0, r1, r2, r3, addr) \
    asm volatile("ldmatrix.sync.aligned.m8n8.x4.shared.b16 {%0,%1,%2,%3}, [%4];" \
        : "=r"(r0), "=r"(r1), "=r"(r2), "=r"(r3) : "r"(addr))

#define MMA_BF16(c, a, b) \
    asm volatile("mma.sync.aligned.m16n8k16.row.col.f32.bf16.bf16.f32 " \
        "{%0,%1,%2,%3}, {%4,%5,%6,%7}, {%8,%9}, {%0,%1,%2,%3};" \
        : "+f"((c)[0]), "+f"((c)[1]), "+f"((c)[2]), "+f"((c)[3]) \
        : "r"((a)[0]), "r"((a)[1]), "r"((a)[2]), "r"((a)[3]), \
          "r"((b)[0]), "r"((b)[1]))

// Exact fp32 score, identical arithmetic order to the validated FFMA kernel:
// dot accumulated by sequential fmaf in ascending d; score = (xsq+wsq) - 2*dot.
__device__ __forceinline__ float exact_score(const float* __restrict__ xr,
                                             float xsq,
                                             const float* __restrict__ W,
                                             const float* __restrict__ WSQ,
                                             int k)
{
    const float4* wr = (const float4*)(W + (size_t)k * DIM);
    float a = 0.f;
    #pragma unroll
    for (int q = 0; q < DIM / 4; q++) {
        float4 b = wr[q];
        a = fmaf(xr[4 * q + 0], b.x, a);
        a = fmaf(xr[4 * q + 1], b.y, a);
        a = fmaf(xr[4 * q + 2], b.z, a);
        a = fmaf(xr[4 * q + 3], b.w, a);
    }
    return __fsub_rn(__fadd_rn(xsq, WSQ[k]), __fmul_rn(2.f, a));
}

// ---------------- prep: W -> bf16 hi + wsq (16 blocks x 32 thr, 1 code/thread) ----------------
__global__ void vq_prep(const float* __restrict__ W) {
    int k = blockIdx.x * 32 + threadIdx.x;   // k in [0, 512)
    const float4* wr = (const float4*)(W + (size_t)k * DIM);
    float4 v[16];
    #pragma unroll
    for (int q = 0; q < 16; q++) v[q] = wr[q];   // pipelined independent loads
    float w[DIM];
    #pragma unroll
    for (int q = 0; q < 16; q++) {
        w[4 * q + 0] = v[q].x; w[4 * q + 1] = v[q].y;
        w[4 * q + 2] = v[q].z; w[4 * q + 3] = v[q].w;
    }
    float s = 0.f;
    #pragma unroll
    for (int d = 0; d < DIM; d++) s = __fadd_rn(s, __fmul_rn(w[d], w[d]));
    g_wsq[k] = s;
    uint2* dst = (uint2*)(g_Whi + (size_t)k * DIM);
    #pragma unroll
    for (int q = 0; q < 16; q++) {
        __nv_bfloat162 p0 = __halves2bfloat162(__float2bfloat16(w[4 * q + 0]),
                                               __float2bfloat16(w[4 * q + 1]));
        __nv_bfloat162 p1 = __halves2bfloat162(__float2bfloat16(w[4 * q + 2]),
                                               __float2bfloat16(w[4 * q + 3]));
        uint2 o;
        o.x = *(uint32_t*)&p0;
        o.y = *(uint32_t*)&p1;
        dst[q] = o;
    }
}

// ---------------- main ----------------
__global__ void __launch_bounds__(THREADS, 1) vq_main(
    const float* __restrict__ x, const float* __restrict__ W,
    float* __restrict__ qout, float* __restrict__ idx_out)
{
    extern __shared__ char smc[];
    const uint32_t smb = smem_u32(smc);
    const int tid = threadIdx.x, wid = tid >> 5, lid = tid & 31;
    float* XS   = (float*)(smc + SM_XS);
    float* WSQ  = (float*)(smc + SM_WSQ);
    float* XSQ  = (float*)(smc + SM_XSQ);
    int*   IDX  = (int*)(smc + SM_IDX);

    // ---- warp-specialized prologue ----
    if (wid < 8) {
        // warps 0-7: load x tile (coalesced), then normalize (1 thread/row)
        const float4* xg = (const float4*)(x + (size_t)blockIdx.x * (TILE_M * DIM));
        #pragma unroll
        for (int i = tid; i < TILE_M * DIM / 4; i += 256) {
            float4 v4 = xg[i];
            int el = i * 4, r = el >> 6, dd = el & 63;
            float* p = XS + r * 65 + dd;
            p[0] = v4.x; p[1] = v4.y; p[2] = v4.z; p[3] = v4.w;
        }
        asm volatile("bar.sync 1, 256;" ::: "memory");   // warps 0-7 only

        // ---- per-row normalization (exact sequential order) ----
        float v[DIM];
        float* xr = XS + tid * 65;
        #pragma unroll
        for (int d = 0; d < DIM; d++) v[d] = xr[d];
        float sum = 0.f;
        #pragma unroll
        for (int d = 0; d < DIM; d++) sum = __fadd_rn(sum, v[d]);
        float mean = __fmul_rn(sum, 0.015625f);
        float ss = 0.f;
        #pragma unroll
        for (int d = 0; d < DIM; d++) {
            float t = __fadd_rn(v[d], -mean);
            ss = __fadd_rn(ss, __fmul_rn(t, t));
        }
        float stdv  = __fsqrt_rn(__fdiv_rn(ss, 63.f));
        float denom = __fadd_rn(stdv, 1e-7f);
        float xsq = 0.f;
        #pragma unroll
        for (int d = 0; d < DIM; d++) {
            v[d] = __fdiv_rn(__fadd_rn(v[d], -mean), denom);
            xsq = __fadd_rn(xsq, __fmul_rn(v[d], v[d]));
            xr[d] = v[d];                       // keep exact xn for loss/rescore
        }
        // bf16 hi only, padded row for ldmatrix
        uint32_t base = (uint32_t)tid * WPITCH;
        #pragma unroll
        for (int q = 0; q < 8; q++) {
            uint32_t pkh[4];
            #pragma unroll
            for (int m = 0; m < 4; m++) {
                __nv_bfloat162 h2 = __halves2bfloat162(
                    __float2bfloat16(v[q * 8 + 2 * m]),
                    __float2bfloat16(v[q * 8 + 2 * m + 1]));
                pkh[m] = *(uint32_t*)&h2;
            }
            *(uint4*)(smc + SM_A_HI + base + q * 16) =
                make_uint4(pkh[0], pkh[1], pkh[2], pkh[3]);
        }
        XSQ[tid] = xsq;
        ((float*)(smc + SM_MEAN))[tid]  = mean;
        ((float*)(smc + SM_DENOM))[tid] = denom;
    } else {
        // warps 8-15: load W bf16 tile (padded rows) + wsq concurrently
        const int t2 = tid - 256;
        const uint4* gh = (const uint4*)g_Whi;
        #pragma unroll
        for (int i = t2; i < KCODES * 8; i += 256) {    // 8 x uint4 per row
            int row = i >> 3, c = i & 7;
            uint32_t off = (uint32_t)(row * WPITCH + c * 16);
            *(uint4*)(smc + SM_B_HI + off) = gh[i];
        }
        #pragma unroll
        for (int i = t2; i < KCODES; i += 256) WSQ[i] = g_wsq[i];
    }
    __syncthreads();

    // ---- warp MMA screening: C[256,512] = Xhi * Whi^T (16 warps x 16 rows) ----
    {
        const int g = lid >> 2, t = lid & 3;
        const int row0 = wid * 16 + g, row1 = row0 + 8;

        // A fragment addresses (lane-mapped for ldmatrix.x4)
        const uint32_t aRow  = (uint32_t)(wid * 16 + ((lid & 8) ? 8 : 0) + (lid & 7));
        const uint32_t aKoff = (lid & 16) ? 16u : 0u;
        const uint32_t aHiA = smb + SM_A_HI + aRow * WPITCH + aKoff;

        uint32_t Ah[4][4];
        #pragma unroll
        for (int kc = 0; kc < 4; kc++)
            LDSM_X4(Ah[kc][0], Ah[kc][1], Ah[kc][2], Ah[kc][3], aHiA + kc * 32);

        // B fragment lane mapping
        const uint32_t bRsel = ((lid & 16) ? 8u : 0u) + (uint32_t)(lid & 7);
        const uint32_t bKoff = (lid & 8) ? 16u : 0u;

        // per-lane top-2 (screening scores, xsq-less) for each of the 2 rows
        float b1r0 = 3.402823466e38f, b2r0 = 3.402823466e38f;
        float b1r1 = 3.402823466e38f, b2r1 = 3.402823466e38f;
        int i1r0 = 0, i2r0 = 0, i1r1 = 0, i2r1 = 0;

        #pragma unroll 1
        for (int nc = 0; nc < 8; nc++) {
            float acc[8][4];
            #pragma unroll
            for (int i = 0; i < 8; i++) {
                acc[i][0] = 0.f; acc[i][1] = 0.f; acc[i][2] = 0.f; acc[i][3] = 0.f;
            }
            #pragma unroll
            for (int kc = 0; kc < 4; kc++) {
                uint32_t bh[8][2];
                #pragma unroll
                for (int p = 0; p < 4; p++) {
                    uint32_t nrow = (uint32_t)(nc * 64 + p * 16) + bRsel;
                    uint32_t boff = nrow * WPITCH + (uint32_t)kc * 32 + bKoff;
                    LDSM_X4(bh[2 * p][0], bh[2 * p][1], bh[2 * p + 1][0], bh[2 * p + 1][1],
                            smb + SM_B_HI + boff);
                }
                #pragma unroll
                for (int nt = 0; nt < 8; nt++)
                    MMA_BF16(acc[nt], Ah[kc], bh[nt]);
            }
            // screening: wsq - 2*dot (xsq row-constant; validated in R9 + rescue)
            #pragma unroll
            for (int nt = 0; nt < 8; nt++) {
                int cb = nc * 64 + nt * 8 + 2 * t;
                float2 w01 = *(const float2*)(WSQ + cb);
                float s;
                s = __fmaf_rn(-2.f, acc[nt][0], w01.x);
                if (s < b1r0) { b2r0 = b1r0; i2r0 = i1r0; b1r0 = s; i1r0 = cb; }
                else if (s < b2r0) { b2r0 = s; i2r0 = cb; }
                s = __fmaf_rn(-2.f, acc[nt][1], w01.y);
                if (s < b1r0) { b2r0 = b1r0; i2r0 = i1r0; b1r0 = s; i1r0 = cb + 1; }
                else if (s < b2r0) { b2r0 = s; i2r0 = cb + 1; }
                s = __fmaf_rn(-2.f, acc[nt][2], w01.x);
                if (s < b1r1) { b2r1 = b1r1; i2r1 = i1r1; b1r1 = s; i1r1 = cb; }
                else if (s < b2r1) { b2r1 = s; i2r1 = cb; }
                s = __fmaf_rn(-2.f, acc[nt][3], w01.y);
                if (s < b1r1) { b2r1 = b1r1; i2r1 = i1r1; b1r1 = s; i1r1 = cb + 1; }
                else if (s < b2r1) { b2r1 = s; i2r1 = cb + 1; }
            }
        }

        // ---- exact fp32 rescore of the per-lane top-2 candidates ----
        const float xsq0 = XSQ[row0], xsq1 = XSQ[row1];
        const float* xr0 = XS + row0 * 65;
        const float* xr1 = XS + row1 * 65;
        float e1 = exact_score(xr0, xsq0, W, WSQ, i1r0);
        float e2 = exact_score(xr0, xsq0, W, WSQ, i2r0);
        float best0; int bi0;
        if (e2 < e1 || (e2 == e1 && i2r0 < i1r0)) { best0 = e2; bi0 = i2r0; }
        else                                      { best0 = e1; bi0 = i1r0; }
        e1 = exact_score(xr1, xsq1, W, WSQ, i1r1);
        e2 = exact_score(xr1, xsq1, W, WSQ, i2r1);
        float best1; int bi1;
        if (e2 < e1 || (e2 == e1 && i2r1 < i1r1)) { best1 = e2; bi1 = i2r1; }
        else                                      { best1 = e1; bi1 = i1r1; }

        // reduce across the 4 lanes sharing a row (tie -> lowest index)
        #pragma unroll
        for (int off = 1; off <= 2; off <<= 1) {
            float sb = __shfl_xor_sync(0xffffffffu, best0, off);
            int   ib = __shfl_xor_sync(0xffffffffu, bi0, off);
            if (sb < best0 || (sb == best0 && ib < bi0)) { best0 = sb; bi0 = ib; }
            sb = __shfl_xor_sync(0xffffffffu, best1, off);
            ib = __shfl_xor_sync(0xffffffffu, bi1, off);
            if (sb < best1 || (sb == best1 && ib < bi1)) { best1 = sb; bi1 = ib; }
        }
        if (t == 0) { IDX[row0] = bi0; IDX[row1] = bi1; }
    }
    __syncthreads();

    // ---- exact gather/loss/denorm (tid < 256, 1 row/thread) ----
    if (tid < TILE_M) {
        int bi = IDX[tid];
        if (idx_out)
            idx_out[(size_t)blockIdx.x * TILE_M + tid] = (float)bi;
        float mean  = ((float*)(smc + SM_MEAN))[tid];
        float denom = ((float*)(smc + SM_DENOM))[tid];
        const float4* wr = (const float4*)(W + (size_t)bi * DIM);
        float* xr = XS + tid * 65;
        float lsum = 0.f;
        #pragma unroll
        for (int q = 0; q < DIM / 4; q++) {
            float4 b = wr[q];
            float d0 = b.x - xr[4 * q + 0];
            float d1 = b.y - xr[4 * q + 1];
            float d2 = b.z - xr[4 * q + 2];
            float d3 = b.w - xr[4 * q + 3];
            lsum = fmaf(d0, d0, lsum); lsum = fmaf(d1, d1, lsum);
            lsum = fmaf(d2, d2, lsum); lsum = fmaf(d3, d3, lsum);
            xr[4 * q + 0] = fmaf(b.x, denom, mean);
            xr[4 * q + 1] = fmaf(b.y, denom, mean);
            xr[4 * q + 2] = fmaf(b.z, denom, mean);
            xr[4 * q + 3] = fmaf(b.w, denom, mean);
        }
        #pragma unroll
        for (int off = 16; off; off >>= 1)
            lsum = __fadd_rn(lsum, __shfl_down_sync(0xffffffffu, lsum, off));
        if (lid == 0) ((float*)(smc + SM_WACC))[wid] = lsum;
    }
    __syncthreads();

    // ---- coalesced quantized store (all 512 threads) + block loss ----
    {
        float* og = qout + (size_t)blockIdx.x * (TILE_M * DIM);
        #pragma unroll
        for (int i = tid; i < TILE_M * DIM; i += THREADS)
            og[i] = XS[(i >> 6) * 65 + (i & 63)];
        if (tid == 0) {
            float* wa = (float*)(smc + SM_WACC);
            float s = wa[0];
            #pragma unroll
            for (int w2 = 1; w2 < 8; w2++) s = __fadd_rn(s, wa[w2]);
            g_blockSums[blockIdx.x] = s;
        }
    }
}

__global__ void vq_loss_kernel(float* __restrict__ loss_out) {
    __shared__ float sh[256];
    int t = threadIdx.x;
    float s = 0.f;
    #pragma unroll
    for (int i = 0; i < N_TILES / 256; i++)
        s = __fadd_rn(s, g_blockSums[t + i * 256]);
    sh[t] = s;
    __syncthreads();
    #pragma unroll
    for (int off = 128; off > 0; off >>= 1) {
        if (t < off) sh[t] = __fadd_rn(sh[t], sh[t + off]);
        __syncthreads();
    }
    if (t == 0)
        loss_out[0] = 1.25f * sh[0] * (1.0f / 16777216.0f);
}

extern "C" void kernel_launch(void* const* d_in, const int* in_sizes, int n_in,
                              void* d_out, int out_size)
{
    const float* x = (const float*)d_in[0];
    const float* W = (const float*)d_in[1];
    float* out = (float*)d_out;

    const long long q = (long long)N_ROWS * DIM;  // 16777216
    float* loss_out = nullptr;
    float* idx_out  = nullptr;
    long long osz = (long long)out_size;
    if (osz >= q + 1 + N_ROWS)      { loss_out = out + q; idx_out = out + q + 1; }
    else if (osz == q + N_ROWS)     { idx_out = out + q; }
    else if (osz == q + 1)          { loss_out = out + q; }

    cudaFuncSetAttribute(vq_main, cudaFuncAttributeMaxDynamicSharedMemorySize, SM_TOTAL);
    vq_prep<<<16, 32>>>(W);
    vq_main<<<N_TILES, THREADS, SM_TOTAL>>>(x, W, out, idx_out);
    if (loss_out)
        vq_loss_kernel<<<1, 256>>>(loss_out);
}